// round 7
// baseline (speedup 1.0000x reference)
#include <cuda_runtime.h>
#include <cuda_fp16.h>
#include <cstdint>

#define RR 5
#define BU 4
#define MAX_IN 1024
#define MAX_MU 64
#define MAX_OUT 256
#define MAX_N 50000
#define MAX_E 500000
#define NPART (2 * RR)
#define NBINS (NPART * MAX_N)

// Static scratch
__device__ __half g_Ph[RR * 3 * MAX_IN * MAX_OUT];              // 7.9 MB fp16 P
__device__ __half g_mh[2][(size_t)RR * MAX_N * MAX_OUT];        // 2 x 128 MB fp16 messages
__device__ int    g_cnt[NBINS];
__device__ int    g_off[NBINS];      // scan1 incl -> scan3 excl -> place advances to END
__device__ int    g_pay[NPART * MAX_E];
__device__ int    g_bsum[1024];

// ---------------------------------------------------------------------------
// FA: fused k_P (blocks [0, pBlocks)) + 4-edge vectorized hist (rest).
__global__ void k_fa(const float* __restrict__ att, const float* __restrict__ basis,
                     const float* __restrict__ fc_w,
                     const int* __restrict__ src, const int* __restrict__ dst,
                     int IN, int MU, int OUT, int E, int N, int pBlocks) {
    if ((int)blockIdx.x < pBlocks) {
        __shared__ float wrow[MAX_MU];
        int o  = threadIdx.x;
        int i  = blockIdx.x % IN;
        int rk = blockIdx.x / IN;
        int r  = rk / 3;
        if (o < MU) {
            float acc = 0.f;
#pragma unroll
            for (int b = 0; b < BU; b++)
                acc += att[r * BU + b] * basis[((size_t)b * IN + i) * MU + o];
            wrow[o] = acc;
        }
        __syncthreads();
        const float* fcb = fc_w + (size_t)(rk * MU) * OUT + o;
        float acc = 0.f;
#pragma unroll 8
        for (int m = 0; m < MU; m++)
            acc = fmaf(wrow[m], fcb[(size_t)m * OUT], acc);
        g_Ph[((size_t)rk * IN + i) * OUT + o] = __float2half_rn(acc);
    } else {
        // hist: 4 edges per thread (int4)
        int t = (blockIdx.x - pBlocks) * blockDim.x + threadIdx.x;
        int eq = E >> 2;
        int tot = NPART * eq;
        if (t >= tot) return;
        int e4 = t % eq;
        int p  = t / eq;
        int r  = p % RR;
        const int* karr = (p < RR) ? dst : src;
        int4 kk = *(const int4*)(karr + (size_t)r * E + 4 * e4);
        int* cb = g_cnt + p * N;
        atomicAdd(&cb[kk.x], 1);
        atomicAdd(&cb[kk.y], 1);
        atomicAdd(&cb[kk.z], 1);
        atomicAdd(&cb[kk.w], 1);
    }
}

// --------------------------- scan ------------------------------------------
__global__ void k_scan1(int n) {
    __shared__ int sh[512];
    int tid = threadIdx.x;
    int i = blockIdx.x * 512 + tid;
    int v = (i < n) ? g_cnt[i] : 0;
    sh[tid] = v;
    __syncthreads();
#pragma unroll
    for (int ofs = 1; ofs < 512; ofs <<= 1) {
        int t = (tid >= ofs) ? sh[tid - ofs] : 0;
        __syncthreads();
        sh[tid] += t;
        __syncthreads();
    }
    if (i < n) g_off[i] = sh[tid];           // inclusive, temp
    if (tid == 511) g_bsum[blockIdx.x] = sh[511];
}

// scan3': per-block reduce of block-sum prefix (scan2 eliminated)
__global__ void k_scan3(int n) {
    __shared__ int ssum[8];
    int tid = threadIdx.x;
    int blk = blockIdx.x >> 1;
    int part = 0;
    for (int t = tid; t < blk; t += 256) part += g_bsum[t];
#pragma unroll
    for (int o = 16; o; o >>= 1) part += __shfl_down_sync(0xFFFFFFFFu, part, o);
    if ((tid & 31) == 0) ssum[tid >> 5] = part;
    __syncthreads();
    int S = 0;
#pragma unroll
    for (int w = 0; w < 8; w++) S += ssum[w];
    int i = blockIdx.x * 256 + tid;
    if (i < n) g_off[i] = g_off[i] - g_cnt[i] + S;   // exclusive offset
}

// ---------------------------------------------------------------------------
// FC: fused place (4-edge int4) + k_m (half2 arithmetic).
__global__ void k_fc(const int* __restrict__ src, const int* __restrict__ dst,
                     const int* __restrict__ drug_feat, const int* __restrict__ dis_feat,
                     const float* __restrict__ cj_drug, const float* __restrict__ cj_dis,
                     int E, int N, int IN, int placeBlocks) {
    if ((int)blockIdx.x < placeBlocks) {
        int t = blockIdx.x * blockDim.x + threadIdx.x;
        int eq = E >> 2;
        int tot = NPART * eq;
        if (t >= tot) return;
        int e4 = t % eq;
        int p  = t / eq;
        int r  = p % RR;
        const int* karr = (p < RR) ? dst : src;
        const int* parr = (p < RR) ? src : dst;
        int4 kk = *(const int4*)(karr + (size_t)r * E + 4 * e4);
        int4 pp = *(const int4*)(parr + (size_t)r * E + 4 * e4);
        int* ob = g_off + p * N;
        g_pay[atomicAdd(&ob[kk.x], 1)] = pp.x;
        g_pay[atomicAdd(&ob[kk.y], 1)] = pp.y;
        g_pay[atomicAdd(&ob[kk.z], 1)] = pp.z;
        g_pay[atomicAdd(&ob[kk.w], 1)] = pp.w;
    } else {
        int gw = ((blockIdx.x - placeBlocks) * blockDim.x + threadIdx.x) >> 5;
        int lane = threadIdx.x & 31;
        if (gw >= 2 * N) return;
        int type = gw >= N;
        int n = gw - type * N;
        const int* feat = type ? dis_feat : drug_feat;
        float c = (type ? cj_dis : cj_drug)[n];
        __half2 ch = __float2half2_rn(c);
        int f0 = feat[n * 3 + 0];
        int f1 = feat[n * 3 + 1];
        int f2 = feat[n * 3 + 2];
        int base = lane * 8;
        __half* mbase = g_mh[type] + (size_t)n * 256 + base;
#pragma unroll
        for (int r = 0; r < RR; r++) {
            uint4 ua = *(const uint4*)(g_Ph + ((size_t)(r * 3 + 0) * IN + f0) * 256 + base);
            uint4 ub = *(const uint4*)(g_Ph + ((size_t)(r * 3 + 1) * IN + f1) * 256 + base);
            uint4 ud = *(const uint4*)(g_Ph + ((size_t)(r * 3 + 2) * IN + f2) * 256 + base);
            uint4 pack;
            const unsigned int* pa = &ua.x;
            const unsigned int* pb = &ub.x;
            const unsigned int* pd = &ud.x;
            unsigned int* po = &pack.x;
#pragma unroll
            for (int q = 0; q < 4; q++) {
                __half2 ha = *(const __half2*)&pa[q];
                __half2 hb = *(const __half2*)&pb[q];
                __half2 hd = *(const __half2*)&pd[q];
                __half2 h = __hmul2(ch, __hadd2(__hadd2(ha, hb), hd));
                po[q] = *(const unsigned int*)&h;
            }
            *(uint4*)(mbase + (size_t)r * N * 256) = pack;
        }
    }
}

// ---------------------------------------------------------------------------
// Fused gather: both directions in one launch. One warp per (dir, node).
// m-row loads use __ldcg (L2-only); next iteration's pay indices prefetched.
__global__ void k_gather(const float* __restrict__ ci_dis, const float* __restrict__ ci_drug,
                         const float* __restrict__ bias,
                         float* __restrict__ out, int N, int gBlocks) {
    int dir = (int)blockIdx.x >= gBlocks;
    int bb_ = blockIdx.x - dir * gBlocks;
    int n = (bb_ * blockDim.x + threadIdx.x) >> 5;
    int lane = threadIdx.x & 31;
    if (n >= N) return;
    int base = lane * 8;
    float acc0 = 0.f, acc1 = 0.f, acc2 = 0.f, acc3 = 0.f;
    float acc4 = 0.f, acc5 = 0.f, acc6 = 0.f, acc7 = 0.f;

#pragma unroll
    for (int r = 0; r < RR; r++) {
        int bin = (dir * RR + r) * N + n;
        int s1 = g_off[bin];                 // end (post-place)
        int s0 = s1 - g_cnt[bin];
        const __half* mb = g_mh[dir] + (size_t)r * N * 256;
        int j = s0;
        if (j + 3 < s1) {
            int ia = g_pay[j + 0], ib = g_pay[j + 1];
            int ic = g_pay[j + 2], id = g_pay[j + 3];
            for (; j + 3 < s1; ) {
                j += 4;
                int na = 0, nb = 0, nc = 0, nd = 0;
                bool more = (j + 3 < s1);
                if (more) {
                    na = g_pay[j + 0]; nb = g_pay[j + 1];
                    nc = g_pay[j + 2]; nd = g_pay[j + 3];
                }
                uint4 va = __ldcg((const uint4*)(mb + (size_t)ia * 256 + base));
                uint4 vb = __ldcg((const uint4*)(mb + (size_t)ib * 256 + base));
                uint4 vc = __ldcg((const uint4*)(mb + (size_t)ic * 256 + base));
                uint4 vd = __ldcg((const uint4*)(mb + (size_t)id * 256 + base));
                float2 f;
                f = __half22float2(*(const __half2*)&va.x); acc0 += f.x; acc1 += f.y;
                f = __half22float2(*(const __half2*)&va.y); acc2 += f.x; acc3 += f.y;
                f = __half22float2(*(const __half2*)&va.z); acc4 += f.x; acc5 += f.y;
                f = __half22float2(*(const __half2*)&va.w); acc6 += f.x; acc7 += f.y;
                f = __half22float2(*(const __half2*)&vb.x); acc0 += f.x; acc1 += f.y;
                f = __half22float2(*(const __half2*)&vb.y); acc2 += f.x; acc3 += f.y;
                f = __half22float2(*(const __half2*)&vb.z); acc4 += f.x; acc5 += f.y;
                f = __half22float2(*(const __half2*)&vb.w); acc6 += f.x; acc7 += f.y;
                f = __half22float2(*(const __half2*)&vc.x); acc0 += f.x; acc1 += f.y;
                f = __half22float2(*(const __half2*)&vc.y); acc2 += f.x; acc3 += f.y;
                f = __half22float2(*(const __half2*)&vc.z); acc4 += f.x; acc5 += f.y;
                f = __half22float2(*(const __half2*)&vc.w); acc6 += f.x; acc7 += f.y;
                f = __half22float2(*(const __half2*)&vd.x); acc0 += f.x; acc1 += f.y;
                f = __half22float2(*(const __half2*)&vd.y); acc2 += f.x; acc3 += f.y;
                f = __half22float2(*(const __half2*)&vd.z); acc4 += f.x; acc5 += f.y;
                f = __half22float2(*(const __half2*)&vd.w); acc6 += f.x; acc7 += f.y;
                ia = na; ib = nb; ic = nc; id = nd;
            }
        }
        for (; j < s1; j++) {
            int sa = g_pay[j];
            uint4 va = __ldcg((const uint4*)(mb + (size_t)sa * 256 + base));
            float2 f;
            f = __half22float2(*(const __half2*)&va.x); acc0 += f.x; acc1 += f.y;
            f = __half22float2(*(const __half2*)&va.y); acc2 += f.x; acc3 += f.y;
            f = __half22float2(*(const __half2*)&va.z); acc4 += f.x; acc5 += f.y;
            f = __half22float2(*(const __half2*)&va.w); acc6 += f.x; acc7 += f.y;
        }
    }

    const float* ci = dir ? ci_drug : ci_dis;
    float* outh = out + (dir ? 0 : (size_t)N * 256);
    float c = ci[n];
    const float4* bv = (const float4*)(bias + base);
    float4 bv0 = bv[0], bv1 = bv[1];
    float4 o0, o1;
    o0.x = acc0 * c + bv0.x;  o0.y = acc1 * c + bv0.y;
    o0.z = acc2 * c + bv0.z;  o0.w = acc3 * c + bv0.w;
    o1.x = acc4 * c + bv1.x;  o1.y = acc5 * c + bv1.y;
    o1.z = acc6 * c + bv1.z;  o1.w = acc7 * c + bv1.w;
    float4* op = (float4*)(outh + (size_t)n * 256 + base);
    op[0] = o0;
    op[1] = o1;
}

// ---------------------------------------------------------------------------
extern "C" void kernel_launch(void* const* d_in, const int* in_sizes, int n_in,
                              void* d_out, int out_size) {
    const int*   drug_feat = (const int*)d_in[0];
    const int*   dis_feat  = (const int*)d_in[1];
    const int*   src       = (const int*)d_in[2];
    const int*   dst       = (const int*)d_in[3];
    const float* cj_drug   = (const float*)d_in[4];
    const float* ci_drug   = (const float*)d_in[5];
    const float* cj_dis    = (const float*)d_in[6];
    const float* ci_dis    = (const float*)d_in[7];
    const float* att       = (const float*)d_in[8];
    const float* basis     = (const float*)d_in[9];
    const float* fc_w      = (const float*)d_in[10];
    const float* fc_b      = (const float*)d_in[11];
    float* out = (float*)d_out;

    const int N   = in_sizes[4];
    const int E   = in_sizes[2] / RR;
    const int OUT = in_sizes[11];
    const int MU  = in_sizes[10] / (OUT * 3 * RR);
    const int IN  = in_sizes[9] / (BU * MU);
    const int nbins = NPART * N;

    void* cntPtr = nullptr;
    cudaGetSymbolAddress(&cntPtr, g_cnt);
    cudaMemsetAsync(cntPtr, 0, (size_t)nbins * sizeof(int), 0);

    // FA: k_P (pBlocks) + 4-edge hist
    const int pBlocks = RR * 3 * IN;
    const int histThreads = NPART * (E >> 2);
    const int histBlocks = (histThreads + 255) / 256;
    k_fa<<<pBlocks + histBlocks, 256>>>(att, basis, fc_w, src, dst,
                                        IN, MU, OUT, E, N, pBlocks);

    // scan
    k_scan1<<<(nbins + 511) / 512, 512>>>(nbins);
    k_scan3<<<(nbins + 255) / 256, 256>>>(nbins);

    // FC: place (4-edge) + k_m (half2)
    const int placeBlocks = histBlocks;
    const int mBlocks = (int)(((long long)2 * N * 32 + 255) / 256);
    k_fc<<<placeBlocks + mBlocks, 256>>>(src, dst, drug_feat, dis_feat,
                                         cj_drug, cj_dis, E, N, IN, placeBlocks);

    // Fused gather (both directions)
    const int gBlocks = (int)(((long long)N * 32 + 255) / 256);
    k_gather<<<2 * gBlocks, 256>>>(ci_dis, ci_drug, fc_b, out, N, gBlocks);
}

// round 8
// speedup vs baseline: 1.0206x; 1.0206x over previous
#include <cuda_runtime.h>
#include <cuda_fp16.h>
#include <cstdint>

#define RR 5
#define BU 4
#define MAX_IN 1024
#define MAX_MU 64
#define MAX_OUT 256
#define MAX_N 50000
#define MAX_E 500000
#define NPART (2 * RR)
#define NBINS (NPART * MAX_N)

// Static scratch
__device__ __half g_Ph[RR * 3 * MAX_IN * MAX_OUT];              // 7.9 MB fp16 P
__device__ __half g_mh[2][(size_t)RR * MAX_N * MAX_OUT];        // 2 x 128 MB fp16 messages
__device__ int    g_cnt[NBINS];
__device__ int    g_off[NBINS];      // scan1 incl -> scan3 excl -> place advances to END
__device__ int    g_pay[NPART * MAX_E];
__device__ int    g_bsum[1024];

// ---------------------------------------------------------------------------
// FA: fused k_P (blocks [0, pBlocks)) + 4-edge vectorized hist (rest).
__global__ void k_fa(const float* __restrict__ att, const float* __restrict__ basis,
                     const float* __restrict__ fc_w,
                     const int* __restrict__ src, const int* __restrict__ dst,
                     int IN, int MU, int OUT, int E, int N, int pBlocks) {
    if ((int)blockIdx.x < pBlocks) {
        __shared__ float wrow[MAX_MU];
        int o  = threadIdx.x;
        int i  = blockIdx.x % IN;
        int rk = blockIdx.x / IN;
        int r  = rk / 3;
        if (o < MU) {
            float acc = 0.f;
#pragma unroll
            for (int b = 0; b < BU; b++)
                acc += att[r * BU + b] * basis[((size_t)b * IN + i) * MU + o];
            wrow[o] = acc;
        }
        __syncthreads();
        const float* fcb = fc_w + (size_t)(rk * MU) * OUT + o;
        float acc = 0.f;
#pragma unroll 8
        for (int m = 0; m < MU; m++)
            acc = fmaf(wrow[m], fcb[(size_t)m * OUT], acc);
        g_Ph[((size_t)rk * IN + i) * OUT + o] = __float2half_rn(acc);
    } else {
        // hist: 4 edges per thread (int4)
        int t = (blockIdx.x - pBlocks) * blockDim.x + threadIdx.x;
        int eq = E >> 2;
        int tot = NPART * eq;
        if (t >= tot) return;
        int e4 = t % eq;
        int p  = t / eq;
        int r  = p % RR;
        const int* karr = (p < RR) ? dst : src;
        int4 kk = *(const int4*)(karr + (size_t)r * E + 4 * e4);
        int* cb = g_cnt + p * N;
        atomicAdd(&cb[kk.x], 1);
        atomicAdd(&cb[kk.y], 1);
        atomicAdd(&cb[kk.z], 1);
        atomicAdd(&cb[kk.w], 1);
    }
}

// --------------------------- scan ------------------------------------------
__global__ void k_scan1(int n) {
    __shared__ int sh[512];
    int tid = threadIdx.x;
    int i = blockIdx.x * 512 + tid;
    int v = (i < n) ? g_cnt[i] : 0;
    sh[tid] = v;
    __syncthreads();
#pragma unroll
    for (int ofs = 1; ofs < 512; ofs <<= 1) {
        int t = (tid >= ofs) ? sh[tid - ofs] : 0;
        __syncthreads();
        sh[tid] += t;
        __syncthreads();
    }
    if (i < n) g_off[i] = sh[tid];           // inclusive, temp
    if (tid == 511) g_bsum[blockIdx.x] = sh[511];
}

// scan3': per-block reduce of block-sum prefix (scan2 eliminated)
__global__ void k_scan3(int n) {
    __shared__ int ssum[8];
    int tid = threadIdx.x;
    int blk = blockIdx.x >> 1;
    int part = 0;
    for (int t = tid; t < blk; t += 256) part += g_bsum[t];
#pragma unroll
    for (int o = 16; o; o >>= 1) part += __shfl_down_sync(0xFFFFFFFFu, part, o);
    if ((tid & 31) == 0) ssum[tid >> 5] = part;
    __syncthreads();
    int S = 0;
#pragma unroll
    for (int w = 0; w < 8; w++) S += ssum[w];
    int i = blockIdx.x * 256 + tid;
    if (i < n) g_off[i] = g_off[i] - g_cnt[i] + S;   // exclusive offset
}

// ---------------------------------------------------------------------------
// FC: fused place (4-edge int4) + k_m (fp32 math, 15 P-row loads batched upfront).
__global__ void k_fc(const int* __restrict__ src, const int* __restrict__ dst,
                     const int* __restrict__ drug_feat, const int* __restrict__ dis_feat,
                     const float* __restrict__ cj_drug, const float* __restrict__ cj_dis,
                     int E, int N, int IN, int placeBlocks) {
    if ((int)blockIdx.x < placeBlocks) {
        int t = blockIdx.x * blockDim.x + threadIdx.x;
        int eq = E >> 2;
        int tot = NPART * eq;
        if (t >= tot) return;
        int e4 = t % eq;
        int p  = t / eq;
        int r  = p % RR;
        const int* karr = (p < RR) ? dst : src;
        const int* parr = (p < RR) ? src : dst;
        int4 kk = *(const int4*)(karr + (size_t)r * E + 4 * e4);
        int4 pp = *(const int4*)(parr + (size_t)r * E + 4 * e4);
        int* ob = g_off + p * N;
        g_pay[atomicAdd(&ob[kk.x], 1)] = pp.x;
        g_pay[atomicAdd(&ob[kk.y], 1)] = pp.y;
        g_pay[atomicAdd(&ob[kk.z], 1)] = pp.z;
        g_pay[atomicAdd(&ob[kk.w], 1)] = pp.w;
    } else {
        int gw = ((blockIdx.x - placeBlocks) * blockDim.x + threadIdx.x) >> 5;
        int lane = threadIdx.x & 31;
        if (gw >= 2 * N) return;
        int type = gw >= N;
        int n = gw - type * N;
        const int* feat = type ? dis_feat : drug_feat;
        float c = (type ? cj_dis : cj_drug)[n];
        int f0 = feat[n * 3 + 0];
        int f1 = feat[n * 3 + 1];
        int f2 = feat[n * 3 + 2];
        int base = lane * 8;
        __half* mbase = g_mh[type] + (size_t)n * 256 + base;

        // Batch ALL 15 row loads first (MLP=15)
        uint4 ua[RR], ub[RR], ud[RR];
#pragma unroll
        for (int r = 0; r < RR; r++) {
            ua[r] = *(const uint4*)(g_Ph + ((size_t)(r * 3 + 0) * IN + f0) * 256 + base);
            ub[r] = *(const uint4*)(g_Ph + ((size_t)(r * 3 + 1) * IN + f1) * 256 + base);
            ud[r] = *(const uint4*)(g_Ph + ((size_t)(r * 3 + 2) * IN + f2) * 256 + base);
        }
#pragma unroll
        for (int r = 0; r < RR; r++) {
            uint4 pack;
            const unsigned int* pa = &ua[r].x;
            const unsigned int* pb = &ub[r].x;
            const unsigned int* pd = &ud[r].x;
            unsigned int* po = &pack.x;
#pragma unroll
            for (int q = 0; q < 4; q++) {
                float2 fa = __half22float2(*(const __half2*)&pa[q]);
                float2 fb = __half22float2(*(const __half2*)&pb[q]);
                float2 fd = __half22float2(*(const __half2*)&pd[q]);
                __half2 h = __floats2half2_rn(c * (fa.x + fb.x + fd.x),
                                              c * (fa.y + fb.y + fd.y));
                po[q] = *(const unsigned int*)&h;
            }
            *(uint4*)(mbase + (size_t)r * N * 256) = pack;
        }
    }
}

// ---------------------------------------------------------------------------
// Fused gather: both directions in one launch. One warp per (dir, node).
// (Round-6 form: simple 4-wide loop, default-cached loads.)
__global__ void k_gather(const float* __restrict__ ci_dis, const float* __restrict__ ci_drug,
                         const float* __restrict__ bias,
                         float* __restrict__ out, int N, int gBlocks) {
    int dir = (int)blockIdx.x >= gBlocks;
    int bb_ = blockIdx.x - dir * gBlocks;
    int n = (bb_ * blockDim.x + threadIdx.x) >> 5;
    int lane = threadIdx.x & 31;
    if (n >= N) return;
    int base = lane * 8;
    float acc0 = 0.f, acc1 = 0.f, acc2 = 0.f, acc3 = 0.f;
    float acc4 = 0.f, acc5 = 0.f, acc6 = 0.f, acc7 = 0.f;

#pragma unroll
    for (int r = 0; r < RR; r++) {
        int bin = (dir * RR + r) * N + n;
        int s1 = g_off[bin];                 // end (post-place)
        int s0 = s1 - g_cnt[bin];
        const __half* mb = g_mh[dir] + (size_t)r * N * 256;
        int j = s0;
        for (; j + 3 < s1; j += 4) {
            int sa = g_pay[j + 0];
            int sb = g_pay[j + 1];
            int sc = g_pay[j + 2];
            int sd = g_pay[j + 3];
            uint4 va = *(const uint4*)(mb + (size_t)sa * 256 + base);
            uint4 vb = *(const uint4*)(mb + (size_t)sb * 256 + base);
            uint4 vc = *(const uint4*)(mb + (size_t)sc * 256 + base);
            uint4 vd = *(const uint4*)(mb + (size_t)sd * 256 + base);
            float2 f;
            f = __half22float2(*(const __half2*)&va.x); acc0 += f.x; acc1 += f.y;
            f = __half22float2(*(const __half2*)&va.y); acc2 += f.x; acc3 += f.y;
            f = __half22float2(*(const __half2*)&va.z); acc4 += f.x; acc5 += f.y;
            f = __half22float2(*(const __half2*)&va.w); acc6 += f.x; acc7 += f.y;
            f = __half22float2(*(const __half2*)&vb.x); acc0 += f.x; acc1 += f.y;
            f = __half22float2(*(const __half2*)&vb.y); acc2 += f.x; acc3 += f.y;
            f = __half22float2(*(const __half2*)&vb.z); acc4 += f.x; acc5 += f.y;
            f = __half22float2(*(const __half2*)&vb.w); acc6 += f.x; acc7 += f.y;
            f = __half22float2(*(const __half2*)&vc.x); acc0 += f.x; acc1 += f.y;
            f = __half22float2(*(const __half2*)&vc.y); acc2 += f.x; acc3 += f.y;
            f = __half22float2(*(const __half2*)&vc.z); acc4 += f.x; acc5 += f.y;
            f = __half22float2(*(const __half2*)&vc.w); acc6 += f.x; acc7 += f.y;
            f = __half22float2(*(const __half2*)&vd.x); acc0 += f.x; acc1 += f.y;
            f = __half22float2(*(const __half2*)&vd.y); acc2 += f.x; acc3 += f.y;
            f = __half22float2(*(const __half2*)&vd.z); acc4 += f.x; acc5 += f.y;
            f = __half22float2(*(const __half2*)&vd.w); acc6 += f.x; acc7 += f.y;
        }
        for (; j < s1; j++) {
            int sa = g_pay[j];
            uint4 va = *(const uint4*)(mb + (size_t)sa * 256 + base);
            float2 f;
            f = __half22float2(*(const __half2*)&va.x); acc0 += f.x; acc1 += f.y;
            f = __half22float2(*(const __half2*)&va.y); acc2 += f.x; acc3 += f.y;
            f = __half22float2(*(const __half2*)&va.z); acc4 += f.x; acc5 += f.y;
            f = __half22float2(*(const __half2*)&va.w); acc6 += f.x; acc7 += f.y;
        }
    }

    const float* ci = dir ? ci_drug : ci_dis;
    float* outh = out + (dir ? 0 : (size_t)N * 256);
    float c = ci[n];
    const float4* bv = (const float4*)(bias + base);
    float4 bv0 = bv[0], bv1 = bv[1];
    float4 o0, o1;
    o0.x = acc0 * c + bv0.x;  o0.y = acc1 * c + bv0.y;
    o0.z = acc2 * c + bv0.z;  o0.w = acc3 * c + bv0.w;
    o1.x = acc4 * c + bv1.x;  o1.y = acc5 * c + bv1.y;
    o1.z = acc6 * c + bv1.z;  o1.w = acc7 * c + bv1.w;
    float4* op = (float4*)(outh + (size_t)n * 256 + base);
    op[0] = o0;
    op[1] = o1;
}

// ---------------------------------------------------------------------------
extern "C" void kernel_launch(void* const* d_in, const int* in_sizes, int n_in,
                              void* d_out, int out_size) {
    const int*   drug_feat = (const int*)d_in[0];
    const int*   dis_feat  = (const int*)d_in[1];
    const int*   src       = (const int*)d_in[2];
    const int*   dst       = (const int*)d_in[3];
    const float* cj_drug   = (const float*)d_in[4];
    const float* ci_drug   = (const float*)d_in[5];
    const float* cj_dis    = (const float*)d_in[6];
    const float* ci_dis    = (const float*)d_in[7];
    const float* att       = (const float*)d_in[8];
    const float* basis     = (const float*)d_in[9];
    const float* fc_w      = (const float*)d_in[10];
    const float* fc_b      = (const float*)d_in[11];
    float* out = (float*)d_out;

    const int N   = in_sizes[4];
    const int E   = in_sizes[2] / RR;
    const int OUT = in_sizes[11];
    const int MU  = in_sizes[10] / (OUT * 3 * RR);
    const int IN  = in_sizes[9] / (BU * MU);
    const int nbins = NPART * N;

    void* cntPtr = nullptr;
    cudaGetSymbolAddress(&cntPtr, g_cnt);
    cudaMemsetAsync(cntPtr, 0, (size_t)nbins * sizeof(int), 0);

    // FA: k_P (pBlocks) + 4-edge hist
    const int pBlocks = RR * 3 * IN;
    const int histThreads = NPART * (E >> 2);
    const int histBlocks = (histThreads + 255) / 256;
    k_fa<<<pBlocks + histBlocks, 256>>>(att, basis, fc_w, src, dst,
                                        IN, MU, OUT, E, N, pBlocks);

    // scan
    k_scan1<<<(nbins + 511) / 512, 512>>>(nbins);
    k_scan3<<<(nbins + 255) / 256, 256>>>(nbins);

    // FC: place (4-edge) + k_m (batched loads)
    const int placeBlocks = histBlocks;
    const int mBlocks = (int)(((long long)2 * N * 32 + 255) / 256);
    k_fc<<<placeBlocks + mBlocks, 256>>>(src, dst, drug_feat, dis_feat,
                                         cj_drug, cj_dis, E, N, IN, placeBlocks);

    // Fused gather (both directions)
    const int gBlocks = (int)(((long long)N * 32 + 255) / 256);
    k_gather<<<2 * gBlocks, 256>>>(ci_dis, ci_drug, fc_b, out, N, gBlocks);
}

// round 9
// speedup vs baseline: 1.0290x; 1.0083x over previous
#include <cuda_runtime.h>
#include <cuda_fp16.h>
#include <cstdint>

#define RR 5
#define BU 4
#define MAX_IN 1024
#define MAX_MU 64
#define MAX_OUT 256
#define MAX_N 50000
#define MAX_E 500000
#define NPART (2 * RR)
#define NBINS (NPART * MAX_N)

// Static scratch
__device__ __half g_Ph[RR * 3 * MAX_IN * MAX_OUT];              // 7.9 MB fp16 P
__device__ __half g_mh[2][(size_t)RR * MAX_N * MAX_OUT];        // 2 x 128 MB fp16 messages
__device__ int    g_cnt[NBINS];
__device__ int    g_off[NBINS];      // scan1 incl -> scan3 excl -> place advances to END
__device__ int    g_pay[NPART * MAX_E];
__device__ int    g_bsum[1024];

// ---------------------------------------------------------------------------
// FA: fused k_P (blocks [0, pBlocks)) + 4-edge vectorized hist (rest).
__global__ void k_fa(const float* __restrict__ att, const float* __restrict__ basis,
                     const float* __restrict__ fc_w,
                     const int* __restrict__ src, const int* __restrict__ dst,
                     int IN, int MU, int OUT, int E, int N, int pBlocks) {
    if ((int)blockIdx.x < pBlocks) {
        __shared__ float wrow[MAX_MU];
        int o  = threadIdx.x;
        int i  = blockIdx.x % IN;
        int rk = blockIdx.x / IN;
        int r  = rk / 3;
        if (o < MU) {
            float acc = 0.f;
#pragma unroll
            for (int b = 0; b < BU; b++)
                acc += att[r * BU + b] * basis[((size_t)b * IN + i) * MU + o];
            wrow[o] = acc;
        }
        __syncthreads();
        const float* fcb = fc_w + (size_t)(rk * MU) * OUT + o;
        float acc = 0.f;
#pragma unroll 8
        for (int m = 0; m < MU; m++)
            acc = fmaf(wrow[m], fcb[(size_t)m * OUT], acc);
        g_Ph[((size_t)rk * IN + i) * OUT + o] = __float2half_rn(acc);
    } else {
        // hist: 4 edges per thread (int4)
        int t = (blockIdx.x - pBlocks) * blockDim.x + threadIdx.x;
        int eq = E >> 2;
        int tot = NPART * eq;
        if (t >= tot) return;
        int e4 = t % eq;
        int p  = t / eq;
        int r  = p % RR;
        const int* karr = (p < RR) ? dst : src;
        int4 kk = *(const int4*)(karr + (size_t)r * E + 4 * e4);
        int* cb = g_cnt + p * N;
        atomicAdd(&cb[kk.x], 1);
        atomicAdd(&cb[kk.y], 1);
        atomicAdd(&cb[kk.z], 1);
        atomicAdd(&cb[kk.w], 1);
    }
}

// --------------------------- scan ------------------------------------------
__global__ void k_scan1(int n) {
    __shared__ int sh[512];
    int tid = threadIdx.x;
    int i = blockIdx.x * 512 + tid;
    int v = (i < n) ? g_cnt[i] : 0;
    sh[tid] = v;
    __syncthreads();
#pragma unroll
    for (int ofs = 1; ofs < 512; ofs <<= 1) {
        int t = (tid >= ofs) ? sh[tid - ofs] : 0;
        __syncthreads();
        sh[tid] += t;
        __syncthreads();
    }
    if (i < n) g_off[i] = sh[tid];           // inclusive, temp
    if (tid == 511) g_bsum[blockIdx.x] = sh[511];
}

// scan3': per-block reduce of block-sum prefix (scan2 eliminated)
__global__ void k_scan3(int n) {
    __shared__ int ssum[8];
    int tid = threadIdx.x;
    int blk = blockIdx.x >> 1;
    int part = 0;
    for (int t = tid; t < blk; t += 256) part += g_bsum[t];
#pragma unroll
    for (int o = 16; o; o >>= 1) part += __shfl_down_sync(0xFFFFFFFFu, part, o);
    if ((tid & 31) == 0) ssum[tid >> 5] = part;
    __syncthreads();
    int S = 0;
#pragma unroll
    for (int w = 0; w < 8; w++) S += ssum[w];
    int i = blockIdx.x * 256 + tid;
    if (i < n) g_off[i] = g_off[i] - g_cnt[i] + S;   // exclusive offset
}

// ---------------------------------------------------------------------------
// FC: fused place (4-edge int4) + k_m (round-6 structure: per-rating
// load-compute-store, fp32 converts, ~32 regs, high occupancy).
__global__ void k_fc(const int* __restrict__ src, const int* __restrict__ dst,
                     const int* __restrict__ drug_feat, const int* __restrict__ dis_feat,
                     const float* __restrict__ cj_drug, const float* __restrict__ cj_dis,
                     int E, int N, int IN, int placeBlocks) {
    if ((int)blockIdx.x < placeBlocks) {
        int t = blockIdx.x * blockDim.x + threadIdx.x;
        int eq = E >> 2;
        int tot = NPART * eq;
        if (t >= tot) return;
        int e4 = t % eq;
        int p  = t / eq;
        int r  = p % RR;
        const int* karr = (p < RR) ? dst : src;
        const int* parr = (p < RR) ? src : dst;
        int4 kk = *(const int4*)(karr + (size_t)r * E + 4 * e4);
        int4 pp = *(const int4*)(parr + (size_t)r * E + 4 * e4);
        int* ob = g_off + p * N;
        g_pay[atomicAdd(&ob[kk.x], 1)] = pp.x;
        g_pay[atomicAdd(&ob[kk.y], 1)] = pp.y;
        g_pay[atomicAdd(&ob[kk.z], 1)] = pp.z;
        g_pay[atomicAdd(&ob[kk.w], 1)] = pp.w;
    } else {
        int gw = ((blockIdx.x - placeBlocks) * blockDim.x + threadIdx.x) >> 5;
        int lane = threadIdx.x & 31;
        if (gw >= 2 * N) return;
        int type = gw >= N;
        int n = gw - type * N;
        const int* feat = type ? dis_feat : drug_feat;
        float c = (type ? cj_dis : cj_drug)[n];
        int f0 = feat[n * 3 + 0];
        int f1 = feat[n * 3 + 1];
        int f2 = feat[n * 3 + 2];
        int base = lane * 8;
        __half* mbase = g_mh[type] + (size_t)n * 256 + base;
#pragma unroll
        for (int r = 0; r < RR; r++) {
            uint4 ua = *(const uint4*)(g_Ph + ((size_t)(r * 3 + 0) * IN + f0) * 256 + base);
            uint4 ub = *(const uint4*)(g_Ph + ((size_t)(r * 3 + 1) * IN + f1) * 256 + base);
            uint4 ud = *(const uint4*)(g_Ph + ((size_t)(r * 3 + 2) * IN + f2) * 256 + base);
            uint4 pack;
            const unsigned int* pa = &ua.x;
            const unsigned int* pb = &ub.x;
            const unsigned int* pd = &ud.x;
            unsigned int* po = &pack.x;
#pragma unroll
            for (int q = 0; q < 4; q++) {
                float2 fa = __half22float2(*(const __half2*)&pa[q]);
                float2 fb = __half22float2(*(const __half2*)&pb[q]);
                float2 fd = __half22float2(*(const __half2*)&pd[q]);
                __half2 h = __floats2half2_rn(c * (fa.x + fb.x + fd.x),
                                              c * (fa.y + fb.y + fd.y));
                po[q] = *(const unsigned int*)&h;
            }
            *(uint4*)(mbase + (size_t)r * N * 256) = pack;
        }
    }
}

// ---------------------------------------------------------------------------
// Fused gather: both directions in one launch. One warp per (dir, node).
// Bin bounds for all 5 ratings hoisted/batched upfront.
__global__ void k_gather(const float* __restrict__ ci_dis, const float* __restrict__ ci_drug,
                         const float* __restrict__ bias,
                         float* __restrict__ out, int N, int gBlocks) {
    int dir = (int)blockIdx.x >= gBlocks;
    int bb_ = blockIdx.x - dir * gBlocks;
    int n = (bb_ * blockDim.x + threadIdx.x) >> 5;
    int lane = threadIdx.x & 31;
    if (n >= N) return;
    int base = lane * 8;
    float acc0 = 0.f, acc1 = 0.f, acc2 = 0.f, acc3 = 0.f;
    float acc4 = 0.f, acc5 = 0.f, acc6 = 0.f, acc7 = 0.f;

    // Batch all bin bounds upfront (10 uniform loads in flight)
    int e1[RR], e0[RR];
#pragma unroll
    for (int r = 0; r < RR; r++) {
        int bin = (dir * RR + r) * N + n;
        e1[r] = g_off[bin];                  // end (post-place)
        e0[r] = e1[r] - g_cnt[bin];
    }

#pragma unroll
    for (int r = 0; r < RR; r++) {
        int s0 = e0[r], s1 = e1[r];
        const __half* mb = g_mh[dir] + (size_t)r * N * 256;
        int j = s0;
        for (; j + 3 < s1; j += 4) {
            int sa = g_pay[j + 0];
            int sb = g_pay[j + 1];
            int sc = g_pay[j + 2];
            int sd = g_pay[j + 3];
            uint4 va = *(const uint4*)(mb + (size_t)sa * 256 + base);
            uint4 vb = *(const uint4*)(mb + (size_t)sb * 256 + base);
            uint4 vc = *(const uint4*)(mb + (size_t)sc * 256 + base);
            uint4 vd = *(const uint4*)(mb + (size_t)sd * 256 + base);
            float2 f;
            f = __half22float2(*(const __half2*)&va.x); acc0 += f.x; acc1 += f.y;
            f = __half22float2(*(const __half2*)&va.y); acc2 += f.x; acc3 += f.y;
            f = __half22float2(*(const __half2*)&va.z); acc4 += f.x; acc5 += f.y;
            f = __half22float2(*(const __half2*)&va.w); acc6 += f.x; acc7 += f.y;
            f = __half22float2(*(const __half2*)&vb.x); acc0 += f.x; acc1 += f.y;
            f = __half22float2(*(const __half2*)&vb.y); acc2 += f.x; acc3 += f.y;
            f = __half22float2(*(const __half2*)&vb.z); acc4 += f.x; acc5 += f.y;
            f = __half22float2(*(const __half2*)&vb.w); acc6 += f.x; acc7 += f.y;
            f = __half22float2(*(const __half2*)&vc.x); acc0 += f.x; acc1 += f.y;
            f = __half22float2(*(const __half2*)&vc.y); acc2 += f.x; acc3 += f.y;
            f = __half22float2(*(const __half2*)&vc.z); acc4 += f.x; acc5 += f.y;
            f = __half22float2(*(const __half2*)&vc.w); acc6 += f.x; acc7 += f.y;
            f = __half22float2(*(const __half2*)&vd.x); acc0 += f.x; acc1 += f.y;
            f = __half22float2(*(const __half2*)&vd.y); acc2 += f.x; acc3 += f.y;
            f = __half22float2(*(const __half2*)&vd.z); acc4 += f.x; acc5 += f.y;
            f = __half22float2(*(const __half2*)&vd.w); acc6 += f.x; acc7 += f.y;
        }
        for (; j < s1; j++) {
            int sa = g_pay[j];
            uint4 va = *(const uint4*)(mb + (size_t)sa * 256 + base);
            float2 f;
            f = __half22float2(*(const __half2*)&va.x); acc0 += f.x; acc1 += f.y;
            f = __half22float2(*(const __half2*)&va.y); acc2 += f.x; acc3 += f.y;
            f = __half22float2(*(const __half2*)&va.z); acc4 += f.x; acc5 += f.y;
            f = __half22float2(*(const __half2*)&va.w); acc6 += f.x; acc7 += f.y;
        }
    }

    const float* ci = dir ? ci_drug : ci_dis;
    float* outh = out + (dir ? 0 : (size_t)N * 256);
    float c = ci[n];
    const float4* bv = (const float4*)(bias + base);
    float4 bv0 = bv[0], bv1 = bv[1];
    float4 o0, o1;
    o0.x = acc0 * c + bv0.x;  o0.y = acc1 * c + bv0.y;
    o0.z = acc2 * c + bv0.z;  o0.w = acc3 * c + bv0.w;
    o1.x = acc4 * c + bv1.x;  o1.y = acc5 * c + bv1.y;
    o1.z = acc6 * c + bv1.z;  o1.w = acc7 * c + bv1.w;
    float4* op = (float4*)(outh + (size_t)n * 256 + base);
    op[0] = o0;
    op[1] = o1;
}

// ---------------------------------------------------------------------------
extern "C" void kernel_launch(void* const* d_in, const int* in_sizes, int n_in,
                              void* d_out, int out_size) {
    const int*   drug_feat = (const int*)d_in[0];
    const int*   dis_feat  = (const int*)d_in[1];
    const int*   src       = (const int*)d_in[2];
    const int*   dst       = (const int*)d_in[3];
    const float* cj_drug   = (const float*)d_in[4];
    const float* ci_drug   = (const float*)d_in[5];
    const float* cj_dis    = (const float*)d_in[6];
    const float* ci_dis    = (const float*)d_in[7];
    const float* att       = (const float*)d_in[8];
    const float* basis     = (const float*)d_in[9];
    const float* fc_w      = (const float*)d_in[10];
    const float* fc_b      = (const float*)d_in[11];
    float* out = (float*)d_out;

    const int N   = in_sizes[4];
    const int E   = in_sizes[2] / RR;
    const int OUT = in_sizes[11];
    const int MU  = in_sizes[10] / (OUT * 3 * RR);
    const int IN  = in_sizes[9] / (BU * MU);
    const int nbins = NPART * N;

    void* cntPtr = nullptr;
    cudaGetSymbolAddress(&cntPtr, g_cnt);
    cudaMemsetAsync(cntPtr, 0, (size_t)nbins * sizeof(int), 0);

    // FA: k_P (pBlocks) + 4-edge hist
    const int pBlocks = RR * 3 * IN;
    const int histThreads = NPART * (E >> 2);
    const int histBlocks = (histThreads + 255) / 256;
    k_fa<<<pBlocks + histBlocks, 256>>>(att, basis, fc_w, src, dst,
                                        IN, MU, OUT, E, N, pBlocks);

    // scan
    k_scan1<<<(nbins + 511) / 512, 512>>>(nbins);
    k_scan3<<<(nbins + 255) / 256, 256>>>(nbins);

    // FC: place (4-edge) + k_m (round-6 structure)
    const int placeBlocks = histBlocks;
    const int mBlocks = (int)(((long long)2 * N * 32 + 255) / 256);
    k_fc<<<placeBlocks + mBlocks, 256>>>(src, dst, drug_feat, dis_feat,
                                         cj_drug, cj_dis, E, N, IN, placeBlocks);

    // Fused gather (both directions)
    const int gBlocks = (int)(((long long)N * 32 + 255) / 256);
    k_gather<<<2 * gBlocks, 256>>>(ci_dis, ci_drug, fc_b, out, N, gBlocks);
}